// round 5
// baseline (speedup 1.0000x reference)
#include <cuda_runtime.h>
#include <cstdint>

#define B        4
#define T        1024
#define HALF     256      // VALUE_DIM / 2
#define C        256
#define NLAB     64
#define VDIM     512

#define CBLK     256      // contract grid: (l=64) x (ch=4)

// Scratch A[b][l][d] (65536 floats). Invariant: zero at entry to every launch
// (static zero-init; contract kernel consume-and-clears its exclusive slice).
__device__ float g_A[B * NLAB * HALF];

// Scratch output accumulator + completion counter (self-resetting).
__device__ float        g_out[B * C];
__device__ unsigned int g_done;

// ---------------------------------------------------------------------------
// Kernel 1: scatter-accumulate
//   A[b, label[b,t], d] += score[b,t] * weight[idx[b,t], off + d]
// One warp per token; two float4 loads + two float4 vector atomics per lane.
// ---------------------------------------------------------------------------
__global__ void __launch_bounds__(256)
vb_scatter_kernel(const int*   __restrict__ indices,
                  const float* __restrict__ scores,
                  const int*   __restrict__ label,
                  const int*   __restrict__ index_p,
                  const float* __restrict__ weight) {
    const int gwarp = (blockIdx.x * blockDim.x + threadIdx.x) >> 5;  // token
    const int lane  = threadIdx.x & 31;

    const int   idx = indices[gwarp];     // warp-uniform broadcast
    const float sc  = scores[gwarp];
    const int   lab = label[gwarp];
    const int   off = (*index_p == 1) ? HALF : 0;
    const int   b   = gwarp >> 10;        // gwarp = b*T + t

    const float4* wrow = reinterpret_cast<const float4*>(
        weight + (size_t)idx * VDIM + off);
    float4 v0 = __ldg(wrow + lane);
    float4 v1 = __ldg(wrow + lane + 32);
    v0.x *= sc; v0.y *= sc; v0.z *= sc; v0.w *= sc;
    v1.x *= sc; v1.y *= sc; v1.z *= sc; v1.w *= sc;

    float4* dst = reinterpret_cast<float4*>(
        g_A + (size_t)(b * NLAB + lab) * HALF);
    atomicAdd(dst + lane,      v0);
    atomicAdd(dst + lane + 32, v1);
}

// ---------------------------------------------------------------------------
// Kernel 2: contraction + consume-and-clear + last-block publish
//   partial[b,c] = sum_{d in chunk} A[b,l,d] * W[l, off+d, c]  -> g_out atomics
// Block (l, ch): l = bid>>2, ch = bid&3 (64 d's each). Thread = column c.
// Inner loop: 4 batches x 16 explicitly-staged loads -> MLP=16 per thread.
// ---------------------------------------------------------------------------
__global__ void __launch_bounds__(256)
vb_contract_kernel(const float* __restrict__ W,
                   const int*   __restrict__ index_p,
                   float*       __restrict__ out) {
    __shared__ float sA[B][64];
    __shared__ int   s_last;

    const int tid = threadIdx.x;
    const int l   = blockIdx.x >> 2;
    const int ch  = blockIdx.x & 3;
    const int off = (*index_p == 1) ? HALF : 0;

    // Stage A slice and clear it (exclusive ownership -> race-free).
    {
        const int b  = tid >> 6;
        const int dd = tid & 63;
        float* ap = &g_A[(size_t)(b * NLAB + l) * HALF + ch * 64 + dd];
        sA[b][dd] = __ldcg(ap);
        *ap = 0.0f;                      // restore zero invariant for next replay
    }
    __syncthreads();

    const float* Wb = W + ((size_t)l * VDIM + off + ch * 64) * C + tid;

    float a0 = 0.f, a1 = 0.f, a2 = 0.f, a3 = 0.f;

#pragma unroll 1
    for (int batch = 0; batch < 4; batch++) {
        const int d0 = batch * 16;
        float w[16];
#pragma unroll
        for (int i = 0; i < 16; i++)       // 16 independent LDGs in flight
            w[i] = __ldg(Wb + (size_t)(d0 + i) * C);
#pragma unroll
        for (int i = 0; i < 16; i++) {
            a0 += sA[0][d0 + i] * w[i];
            a1 += sA[1][d0 + i] * w[i];
            a2 += sA[2][d0 + i] * w[i];
            a3 += sA[3][d0 + i] * w[i];
        }
    }

    atomicAdd(&g_out[0 * C + tid], a0);
    atomicAdd(&g_out[1 * C + tid], a1);
    atomicAdd(&g_out[2 * C + tid], a2);
    atomicAdd(&g_out[3 * C + tid], a3);

    // Tail: last finished block publishes g_out -> out and clears scratch.
    __threadfence();
    __syncthreads();
    if (tid == 0) {
        const unsigned r = atomicAdd(&g_done, 1u);
        s_last = (r == (unsigned)(CBLK - 1)) ? 1 : 0;
    }
    __syncthreads();

    if (s_last) {
#pragma unroll
        for (int k = 0; k < (B * C) / 256; k++) {
            const int i = k * 256 + tid;
            out[i]   = __ldcg(&g_out[i]);   // sees all blocks' atomics
            g_out[i] = 0.0f;
        }
        if (tid == 0) atomicExch(&g_done, 0u);
    }
}

// ---------------------------------------------------------------------------
// Inputs (metadata order):
//   0: indices (B,T) int32     1: scores (B,T) f32
//   2: W (64,512,256) f32      3: label (B,T) int32
//   4: index scalar int32      5: weight (262144,512) f32
// Output: (B, C) f32 = 1024 floats
// ---------------------------------------------------------------------------
extern "C" void kernel_launch(void* const* d_in, const int* in_sizes, int n_in,
                              void* d_out, int out_size) {
    const int*   indices = (const int*)  d_in[0];
    const float* scores  = (const float*)d_in[1];
    const float* W       = (const float*)d_in[2];
    const int*   label   = (const int*)  d_in[3];
    const int*   index_p = (const int*)  d_in[4];
    const float* weight  = (const float*)d_in[5];
    float*       out     = (float*)d_out;

    // 1) scatter: B*T = 4096 warps -> 512 blocks x 256 threads
    vb_scatter_kernel<<<512, 256>>>(indices, scores, label, index_p, weight);

    // 2) contraction: 64 labels x 4 d-chunks
    vb_contract_kernel<<<CBLK, 256>>>(W, index_p, out);
}